// round 7
// baseline (speedup 1.0000x reference)
#include <cuda_runtime.h>
#include <cuda_fp16.h>
#include <math.h>
#include <stdint.h>

// Problem dims
#define TT   64
#define VV   30000
#define HID  512
#define XD   768          // EMB + E
#define G4   2048         // 4*H
#define MROWS 2048        // B*T

// ---------------- scratch (device globals; no allocation allowed) -------------
__device__ __align__(16) __half g_X2  [MROWS * XD];          // fp16 X
__device__ __align__(16) __half g_Wih2[G4 * XD];             // fp16 W_ih
__device__ __align__(16) __half g_Whh2[G4 * HID];            // fp16 W_hh
__device__ __align__(16) __half g_Wfc2[(size_t)VV * HID];    // fp16 W_fc
__device__ __align__(16) __half g_H2  [MROWS * HID];         // fp16 hidden history
__device__ __align__(16) __half g_h2A [32 * HID];            // h state ping
__device__ __align__(16) __half g_h2B [32 * HID];            // h state pong
__device__ __align__(16) float  g_pg[MROWS * G4];            // pregates fp32
__device__ int g_bar;

// ---------------- small helpers ------------------------------------------------
__device__ __forceinline__ uint32_t smem_u32(const void* p) {
    uint32_t a;
    asm("{ .reg .u64 t; cvta.to.shared.u64 t, %1; cvt.u32.u64 %0, t; }" : "=r"(a) : "l"(p));
    return a;
}
__device__ __forceinline__ void ldsm4(uint32_t* r, uint32_t addr) {
    asm volatile("ldmatrix.sync.aligned.m8n8.x4.shared.b16 {%0,%1,%2,%3}, [%4];"
                 : "=r"(r[0]), "=r"(r[1]), "=r"(r[2]), "=r"(r[3]) : "r"(addr));
}
__device__ __forceinline__ void mma16816(float* d, const uint32_t* a,
                                         uint32_t b0, uint32_t b1) {
    asm volatile("mma.sync.aligned.m16n8k16.row.col.f32.f16.f16.f32 "
                 "{%0,%1,%2,%3}, {%4,%5,%6,%7}, {%8,%9}, {%0,%1,%2,%3};"
                 : "+f"(d[0]), "+f"(d[1]), "+f"(d[2]), "+f"(d[3])
                 : "r"(a[0]), "r"(a[1]), "r"(a[2]), "r"(a[3]), "r"(b0), "r"(b1));
}
__device__ __forceinline__ void cpasync16(uint32_t dst, const void* src) {
    asm volatile("cp.async.cg.shared.global [%0], [%1], 16;" :: "r"(dst), "l"(src));
}
__device__ __forceinline__ void cpasync16z(uint32_t dst, const void* src, unsigned sz) {
    asm volatile("cp.async.cg.shared.global [%0], [%1], 16, %2;"
                 :: "r"(dst), "l"(src), "r"(sz));
}
#define CP_COMMIT() asm volatile("cp.async.commit_group;" ::: "memory")

// ---------------- fp32 -> fp16 convert ----------------------------------------
__global__ void cvt2h_kernel(const float* __restrict__ src,
                             __half* __restrict__ dst, int n2)
{
    int i = blockIdx.x * 256 + threadIdx.x;
    if (i >= n2) return;
    float2 v = ((const float2*)src)[i];
    ((__half2*)dst)[i] = __floats2half2_rn(v.x, v.y);
}

// ---------------- prep: X2 = fp16([emb||enc]); zero FULL h ping + barrier ------
__global__ void prep_kernel(const float* __restrict__ enc,
                            const int*   __restrict__ captions,
                            const float* __restrict__ emb_table,
                            __half* __restrict__ X2,
                            __half* __restrict__ h0, int* __restrict__ bar)
{
    int blk = blockIdx.x;
    if (blk < MROWS) {
        int b = blk >> 6;
        int cap = captions[blk];
        const float* erow = emb_table + (size_t)cap * 512;
        const float* crow = enc + (size_t)b * 256;
        size_t base = (size_t)blk * XD;
        for (int c = threadIdx.x; c < XD; c += 256) {
            float x = (c < 512) ? erow[c] : crow[c - 512];
            X2[base + c] = __float2half(x);
        }
    } else {
        // h0 = 32*512 halves = 8192 uint32; 32 blocks x 256 threads cover all.
        int i = (blk - MROWS) * 256 + threadIdx.x;   // 0..8191
        ((uint32_t*)h0)[i] = 0u;
        if (i == 0) *bar = 0;
    }
}

// ---------------- HMMA GEMM: C[M,N] = A[M,K] B[N,K]^T + bias ------------------
// fp16 in, fp32 out. CTA tile 128x256, 8 warps (2m x 4n), warp tile 64x64.
// A redundancy 2x, B redundancy 2x -> crossbar traffic per MAC halved vs 128x128.
// K-chunk 64, swizzled SMEM (128B rows), 3-stage cp.async pipeline.
#define KC 64
#define STAGE_BYTES 49152      // A 16KB + B 32KB
#define GSMEM (3 * STAGE_BYTES)

__global__ __launch_bounds__(256, 1) void hmma_gemm(
    const __half* __restrict__ A, const __half* __restrict__ B,
    float* __restrict__ C,
    const float* __restrict__ bias0, const float* __restrict__ bias1,
    int M, int N, int K)
{
    extern __shared__ char smem[];
    const uint32_t sb = smem_u32(smem);
    const int tid  = threadIdx.x;
    const int lane = tid & 31, wid = tid >> 5;
    const int m0 = blockIdx.y * 128, n0 = blockIdx.x * 256;
    const int wm = wid & 1, wn = wid >> 1;
    const int nch = K / KC;

    const int rowA = wm * 64 + (lane & 7) + ((lane >> 3) & 1) * 8;
    const int kxA  = ((lane >> 4) * 16) ^ ((rowA & 7) * 16);
    const int rowB = wn * 64 + (lane & 7) + ((lane >= 16) ? 8 : 0);
    const int kxB  = (((lane >> 3) & 1) * 16) ^ ((rowB & 7) * 16);

    float acc[4][8][4];
#pragma unroll
    for (int i = 0; i < 4; i++)
#pragma unroll
        for (int j = 0; j < 8; j++)
#pragma unroll
            for (int e = 0; e < 4; e++) acc[i][j][e] = 0.f;

    const int prow = tid >> 3;      // 0..31 base; +32 per 256-thread step
    const int pcc  = tid & 7;
#define PREFETCH(stage, kt)                                                     \
    do {                                                                        \
        uint32_t ab = sb + (stage) * STAGE_BYTES;                               \
        _Pragma("unroll")                                                       \
        for (int j = 0; j < 4; j++) {        /* A: 128 rows */                  \
            int row = prow + j * 32;                                            \
            uint32_t dst = ab + (uint32_t)(row * 128 + ((pcc * 16) ^ ((row & 7) * 16))); \
            cpasync16(dst, A + (size_t)(m0 + row) * K + (kt) + pcc * 8);        \
        }                                                                       \
        _Pragma("unroll")                                                       \
        for (int j = 0; j < 8; j++) {        /* B: 256 rows */                  \
            int row = prow + j * 32;                                            \
            int gn = n0 + row;                                                  \
            uint32_t dst = ab + 16384u + (uint32_t)(row * 128 + ((pcc * 16) ^ ((row & 7) * 16))); \
            int gnc = gn < N ? gn : N - 1;                                      \
            cpasync16z(dst, B + (size_t)gnc * K + (kt) + pcc * 8,               \
                       gn < N ? 16u : 0u);                                      \
        }                                                                       \
        CP_COMMIT();                                                            \
    } while (0)

    PREFETCH(0, 0);
    PREFETCH(1, KC);

    for (int c = 0; c < nch; c++) {
        if (c + 2 < nch) PREFETCH((c + 2) % 3, (c + 2) * KC);
        if (c + 2 < nch)      asm volatile("cp.async.wait_group 2;" ::: "memory");
        else if (c + 1 < nch) asm volatile("cp.async.wait_group 1;" ::: "memory");
        else                  asm volatile("cp.async.wait_group 0;" ::: "memory");
        __syncthreads();

        const uint32_t As = sb + (c % 3) * STAGE_BYTES;
        const uint32_t Bs = As + 16384;
#pragma unroll
        for (int ks = 0; ks < 4; ks++) {
            uint32_t a[4][4], b[4][4];
#pragma unroll
            for (int mt = 0; mt < 4; mt++)
                ldsm4(a[mt], As + (uint32_t)((rowA + mt * 16) * 128 + ((ks * 32) ^ kxA)));
#pragma unroll
            for (int j = 0; j < 4; j++)
                ldsm4(b[j], Bs + (uint32_t)((rowB + j * 16) * 128 + ((ks * 32) ^ kxB)));
#pragma unroll
            for (int mt = 0; mt < 4; mt++)
#pragma unroll
                for (int nt = 0; nt < 8; nt++)
                    mma16816(acc[mt][nt], a[mt],
                             b[nt >> 1][(nt & 1) * 2], b[nt >> 1][(nt & 1) * 2 + 1]);
        }
        __syncthreads();
    }

    const int mrow  = m0 + wm * 64 + (lane >> 2);
    const int ncol0 = n0 + wn * 64 + (lane & 3) * 2;
#pragma unroll
    for (int mt = 0; mt < 4; mt++) {
#pragma unroll
        for (int nt = 0; nt < 8; nt++) {
            int cc = ncol0 + nt * 8;
            if (cc < N) {
                float b0v = bias0[cc], b1v = bias0[cc + 1];
                if (bias1) { b0v += bias1[cc]; b1v += bias1[cc + 1]; }
                int r0 = mrow + mt * 16;
                float2 v0 = make_float2(acc[mt][nt][0] + b0v, acc[mt][nt][1] + b1v);
                float2 v1 = make_float2(acc[mt][nt][2] + b0v, acc[mt][nt][3] + b1v);
                *(float2*)(C + (size_t)r0 * N + cc)       = v0;
                *(float2*)(C + (size_t)(r0 + 8) * N + cc) = v1;
            }
        }
    }
#undef PREFETCH
}

// ---------------- persistent LSTM, tensor-core recurrence ----------------------
// 64 CTAs x 256 threads (8 warps). CTA owns 8 hidden units -> 32 gate rows.
// W_hh (fp16) SMEM-resident. h: fp16 [32 x 512] ping-pong in L2.
// pregates tile for step t+1 prefetched into double-buffered SMEM during step t
// (cp.async, waited with the h stage via wait_group 1) -> L2 latency off the
// critical path. Grid barrier via monotonic atomic.
#define LWS_OFF  0
#define LHS_OFF  32768
#define LPG_OFF  65536                        // 2 x 4KB pregates buffers
#define LGSM_OFF (65536 + 8192)
#define LCSM_OFF (LGSM_OFF + 32 * 33 * 4)
#define LSM_BYTES (LCSM_OFF + 256 * 4)

__device__ __forceinline__ float sigf(float x) { return 1.0f / (1.0f + expf(-x)); }

__global__ __launch_bounds__(256, 1) void lstm_persistent(
    const float* __restrict__ pregates,
    const __half* __restrict__ Whh2,
    __half* __restrict__ hA, __half* __restrict__ hB,
    __half* __restrict__ H2, int* __restrict__ bar)
{
    extern __shared__ char smem[];
    const uint32_t sb = smem_u32(smem);
    float* gsm = (float*)(smem + LGSM_OFF);
    float* csm = (float*)(smem + LCSM_OFF);

    const int tid  = threadIdx.x;
    const int lane = tid & 31, wid = tid >> 5;
    const int u0   = blockIdx.x * 8;

    // pregates prefetch geometry: thread -> (b, gate, 16B-half)
    const int qb = tid >> 3, qg = (tid >> 1) & 3, qh = tid & 1;
    const size_t qsrc_base = (size_t)qb * TT * G4 + qg * 512 + u0 + qh * 4;
    const uint32_t qdst_off = (uint32_t)(qb * 128 + qg * 32 + qh * 16);

    // stage 32 gate rows of W_hh (fp16) once
    for (int i = tid; i < 2048; i += 256) {
        int rr = i >> 6, cq = i & 63;
        int g = rr >> 3, ul = rr & 7;
        uint32_t dst = sb + LWS_OFF + (uint32_t)(rr * 1024 + ((cq * 16) ^ ((rr & 7) * 16)));
        cpasync16(dst, Whh2 + (size_t)(g * 512 + u0 + ul) * HID + cq * 8);
    }
    CP_COMMIT();
    // prefetch pregates for t = 0 into buffer 0
    cpasync16(sb + LPG_OFF + qdst_off, pregates + qsrc_base);
    CP_COMMIT();
    csm[tid] = 0.0f;

    // warp geometry
    const int wm = wid & 1, wn = wid >> 1;
    const int rowA = wm * 16 + (lane & 15);
    const int kxA  = (lane >> 4) * 16;
    const int sxA  = (rowA & 7) * 16;
    const int rowB = wn * 8 + (lane & 7);
    const int kxB  = ((lane >> 3) & 3) * 16;
    const int sxB  = (rowB & 7) * 16;
    const uint32_t wsb = sb + LWS_OFF, hsb = sb + LHS_OFF;

    const int pb = tid >> 3, pul = tid & 7;
    const int pu = u0 + pul;

    for (int t = 0; t < TT; t++) {
        // stage h (fp16 32x512) into swizzled SMEM
        const __half* hin = (t & 1) ? hB : hA;
        for (int i = tid; i < 2048; i += 256) {
            int b = i >> 6, cq = i & 63;
            uint32_t dst = hsb + (uint32_t)(b * 1024 + ((cq * 16) ^ ((b & 7) * 16)));
            cpasync16(dst, hin + b * HID + cq * 8);
        }
        CP_COMMIT();
        if (t + 1 < TT) {
            // prefetch pregates(t+1) into the other buffer; stays in flight
            cpasync16(sb + LPG_OFF + ((t + 1) & 1) * 4096 + qdst_off,
                      pregates + qsrc_base + (size_t)(t + 1) * G4);
            CP_COMMIT();
            asm volatile("cp.async.wait_group 1;" ::: "memory");
        } else {
            asm volatile("cp.async.wait_group 0;" ::: "memory");
        }
        __syncthreads();

        // MMA: [32 gate-rows x 32 batch] = Ws[32x512] * hs[32x512]^T
        float c0[4] = {0.f, 0.f, 0.f, 0.f}, c1[4] = {0.f, 0.f, 0.f, 0.f};
#pragma unroll
        for (int ks2 = 0; ks2 < 16; ks2++) {
            uint32_t bf[4], a0[4], a1[4];
            ldsm4(bf, hsb + (uint32_t)(rowB * 1024 + ((ks2 * 64 + kxB) ^ sxB)));
            ldsm4(a0, wsb + (uint32_t)(rowA * 1024 + ((ks2 * 64 + kxA) ^ sxA)));
            ldsm4(a1, wsb + (uint32_t)(rowA * 1024 + ((ks2 * 64 + 32 + kxA) ^ sxA)));
            mma16816(c0, a0, bf[0], bf[1]);
            mma16816(c1, a1, bf[2], bf[3]);
        }
#pragma unroll
        for (int e = 0; e < 4; e++) c0[e] += c1[e];
        {
            int r0 = wm * 16 + (lane >> 2);
            int cc = wn * 8 + (lane & 3) * 2;
            gsm[r0 * 33 + cc]           = c0[0];
            gsm[r0 * 33 + cc + 1]       = c0[1];
            gsm[(r0 + 8) * 33 + cc]     = c0[2];
            gsm[(r0 + 8) * 33 + cc + 1] = c0[3];
        }
        __syncthreads();

        // pointwise: 256 threads = 32 b x 8 units; pregates from SMEM buffer
        {
            const float* pgs = (const float*)(smem + LPG_OFF + (t & 1) * 4096);
            float gi = gsm[(0  + pul) * 33 + pb] + pgs[pb * 32 + 0 * 8 + pul];
            float gf = gsm[(8  + pul) * 33 + pb] + pgs[pb * 32 + 1 * 8 + pul];
            float gg = gsm[(16 + pul) * 33 + pb] + pgs[pb * 32 + 2 * 8 + pul];
            float go = gsm[(24 + pul) * 33 + pb] + pgs[pb * 32 + 3 * 8 + pul];
            float c_old = csm[tid];
            float cn = sigf(gf) * c_old + sigf(gi) * tanhf(gg);
            float hn = sigf(go) * tanhf(cn);
            csm[tid] = cn;
            __half hh = __float2half(hn);
            __half* hout = (t & 1) ? hA : hB;
            hout[pb * HID + pu] = hh;
            H2[((size_t)pb * TT + t) * HID + pu] = hh;
        }

        if (t < TT - 1) {
            __threadfence();
            __syncthreads();
            if (tid == 0) {
                atomicAdd(bar, 1);
                int target = 64 * (t + 1);
                while (*((volatile int*)bar) < target) { }
            }
            __syncthreads();
            __threadfence();
        }
    }
}

// ---------------- launch ------------------------------------------------------
extern "C" void kernel_launch(void* const* d_in, const int* in_sizes, int n_in,
                              void* d_out, int out_size)
{
    const float* enc       = (const float*)d_in[0];
    const int*   captions  = (const int*)  d_in[1];
    const float* emb_table = (const float*)d_in[8];
    const float* W_ih      = (const float*)d_in[9];
    const float* W_hh      = (const float*)d_in[10];
    const float* b_ih      = (const float*)d_in[11];
    const float* b_hh      = (const float*)d_in[12];
    const float* W_fc      = (const float*)d_in[13];
    const float* b_fc      = (const float*)d_in[14];
    float* out = (float*)d_out;

    __half *pX2, *pWih2, *pWhh2, *pWfc2, *pH2, *ph2A, *ph2B;
    float *pPG;
    int* pBar;
    cudaGetSymbolAddress((void**)&pX2, g_X2);
    cudaGetSymbolAddress((void**)&pWih2, g_Wih2);
    cudaGetSymbolAddress((void**)&pWhh2, g_Whh2);
    cudaGetSymbolAddress((void**)&pWfc2, g_Wfc2);
    cudaGetSymbolAddress((void**)&pH2, g_H2);
    cudaGetSymbolAddress((void**)&ph2A, g_h2A);
    cudaGetSymbolAddress((void**)&ph2B, g_h2B);
    cudaGetSymbolAddress((void**)&pPG, g_pg);
    cudaGetSymbolAddress((void**)&pBar, g_bar);

    cudaFuncSetAttribute(hmma_gemm, cudaFuncAttributeMaxDynamicSharedMemorySize, GSMEM);
    cudaFuncSetAttribute(lstm_persistent, cudaFuncAttributeMaxDynamicSharedMemorySize, LSM_BYTES);

    // 1) fp32 -> fp16 weight converts
    cvt2h_kernel<<<(G4 * XD / 2 + 255) / 256, 256>>>(W_ih, pWih2, G4 * XD / 2);
    cvt2h_kernel<<<(G4 * HID / 2 + 255) / 256, 256>>>(W_hh, pWhh2, G4 * HID / 2);
    cvt2h_kernel<<<(VV * HID / 2 + 255) / 256, 256>>>(W_fc, pWfc2, VV * HID / 2);

    // 2) build X2, zero FULL h ping + barrier reset
    prep_kernel<<<MROWS + 32, 256>>>(enc, captions, emb_table, pX2, ph2A, pBar);

    // 3) pregates = X @ W_ih^T + b_ih + b_hh   (K = 768, N tile 256)
    {
        dim3 grid(G4 / 256, MROWS / 128);
        hmma_gemm<<<grid, 256, GSMEM>>>(pX2, pWih2, pPG, b_ih, b_hh,
                                        MROWS, G4, XD);
    }

    // 4) persistent tensor-core LSTM (one launch, emits H2 inline)
    lstm_persistent<<<64, 256, LSM_BYTES>>>(pPG, pWhh2, ph2A, ph2B, pH2, pBar);

    // 5) out = H @ W_fc^T + b_fc   (K = 512, N tile 256)
    {
        dim3 grid((VV + 255) / 256, MROWS / 128);
        hmma_gemm<<<grid, 256, GSMEM>>>(pH2, pWfc2, out, b_fc, nullptr,
                                        MROWS, VV, HID);
    }
}

// round 8
// speedup vs baseline: 1.0934x; 1.0934x over previous
#include <cuda_runtime.h>
#include <cuda_fp16.h>
#include <math.h>
#include <stdint.h>

// Problem dims
#define TT   64
#define VV   30000
#define HID  512
#define XD   768          // EMB + E
#define G4   2048         // 4*H
#define MROWS 2048        // B*T

// ---------------- scratch (device globals; no allocation allowed) -------------
__device__ __align__(16) __half g_X2  [MROWS * XD];          // fp16 X
__device__ __align__(16) __half g_Wih2[G4 * XD];             // fp16 W_ih
__device__ __align__(16) __half g_Whh2[G4 * HID];            // fp16 W_hh
__device__ __align__(16) __half g_Wfc2[(size_t)VV * HID];    // fp16 W_fc
__device__ __align__(16) __half g_H2  [MROWS * HID];         // fp16 hidden history
__device__ __align__(16) __half g_h2A [32 * HID];            // h state ping
__device__ __align__(16) __half g_h2B [32 * HID];            // h state pong
__device__ __align__(16) float  g_pg[MROWS * G4];            // pregates fp32
__device__ int g_bar;

// ---------------- small helpers ------------------------------------------------
__device__ __forceinline__ uint32_t smem_u32(const void* p) {
    uint32_t a;
    asm("{ .reg .u64 t; cvta.to.shared.u64 t, %1; cvt.u32.u64 %0, t; }" : "=r"(a) : "l"(p));
    return a;
}
__device__ __forceinline__ void ldsm4(uint32_t* r, uint32_t addr) {
    asm volatile("ldmatrix.sync.aligned.m8n8.x4.shared.b16 {%0,%1,%2,%3}, [%4];"
                 : "=r"(r[0]), "=r"(r[1]), "=r"(r[2]), "=r"(r[3]) : "r"(addr));
}
__device__ __forceinline__ void mma16816(float* d, const uint32_t* a,
                                         uint32_t b0, uint32_t b1) {
    asm volatile("mma.sync.aligned.m16n8k16.row.col.f32.f16.f16.f32 "
                 "{%0,%1,%2,%3}, {%4,%5,%6,%7}, {%8,%9}, {%0,%1,%2,%3};"
                 : "+f"(d[0]), "+f"(d[1]), "+f"(d[2]), "+f"(d[3])
                 : "r"(a[0]), "r"(a[1]), "r"(a[2]), "r"(a[3]), "r"(b0), "r"(b1));
}
__device__ __forceinline__ void cpasync16(uint32_t dst, const void* src) {
    asm volatile("cp.async.cg.shared.global [%0], [%1], 16;" :: "r"(dst), "l"(src));
}
__device__ __forceinline__ void cpasync16z(uint32_t dst, const void* src, unsigned sz) {
    asm volatile("cp.async.cg.shared.global [%0], [%1], 16, %2;"
                 :: "r"(dst), "l"(src), "r"(sz));
}
#define CP_COMMIT() asm volatile("cp.async.commit_group;" ::: "memory")

// ---------------- fp32 -> fp16 convert ----------------------------------------
__global__ void cvt2h_kernel(const float* __restrict__ src,
                             __half* __restrict__ dst, int n2)
{
    int i = blockIdx.x * 256 + threadIdx.x;
    if (i >= n2) return;
    float2 v = ((const float2*)src)[i];
    ((__half2*)dst)[i] = __floats2half2_rn(v.x, v.y);
}

// ---------------- prep: X2 = fp16([emb||enc]); zero FULL h ping + barrier ------
__global__ void prep_kernel(const float* __restrict__ enc,
                            const int*   __restrict__ captions,
                            const float* __restrict__ emb_table,
                            __half* __restrict__ X2,
                            __half* __restrict__ h0, int* __restrict__ bar)
{
    int blk = blockIdx.x;
    if (blk < MROWS) {
        int b = blk >> 6;
        int cap = captions[blk];
        const float* erow = emb_table + (size_t)cap * 512;
        const float* crow = enc + (size_t)b * 256;
        size_t base = (size_t)blk * XD;
        for (int c = threadIdx.x; c < XD; c += 256) {
            float x = (c < 512) ? erow[c] : crow[c - 512];
            X2[base + c] = __float2half(x);
        }
    } else {
        // h0 = 32*512 halves = 8192 uint32; 32 blocks x 256 threads cover all.
        int i = (blk - MROWS) * 256 + threadIdx.x;   // 0..8191
        ((uint32_t*)h0)[i] = 0u;
        if (i == 0) *bar = 0;
    }
}

// ---------------- HMMA GEMM: C[M,N] = A[M,K] B[N,K]^T + bias ------------------
// fp16 in, fp32 out. CTA tile 128x128, 4 warps (2m x 2n), warp tile 64x64.
// A and B redundancy both 2x -> 96KB crossbar/chunk = 768 cyc < 1024 cyc HMMA
// -> tensor-pipe-bound. 2 CTAs/SM (launch_bounds(128,2)) keeps 2 warps/SMSP.
// K-chunk 64, swizzled SMEM (128B rows), 3-stage cp.async pipeline.
#define KC 64
#define STAGE_BYTES 32768      // A 16KB + B 16KB
#define GSMEM (3 * STAGE_BYTES)

__global__ __launch_bounds__(128, 2) void hmma_gemm(
    const __half* __restrict__ A, const __half* __restrict__ B,
    float* __restrict__ C,
    const float* __restrict__ bias0, const float* __restrict__ bias1,
    int M, int N, int K)
{
    extern __shared__ char smem[];
    const uint32_t sb = smem_u32(smem);
    const int tid  = threadIdx.x;
    const int lane = tid & 31, wid = tid >> 5;
    const int m0 = blockIdx.y * 128, n0 = blockIdx.x * 128;
    const int wm = wid & 1, wn = wid >> 1;     // 2 x 2 warps
    const int nch = K / KC;

    const int rowA = wm * 64 + (lane & 7) + ((lane >> 3) & 1) * 8;
    const int kxA  = ((lane >> 4) * 16) ^ ((rowA & 7) * 16);
    const int rowB = wn * 64 + (lane & 7) + ((lane >= 16) ? 8 : 0);
    const int kxB  = (((lane >> 3) & 1) * 16) ^ ((rowB & 7) * 16);

    float acc[4][8][4];
#pragma unroll
    for (int i = 0; i < 4; i++)
#pragma unroll
        for (int j = 0; j < 8; j++)
#pragma unroll
            for (int e = 0; e < 4; e++) acc[i][j][e] = 0.f;

    const int prow = tid >> 3;      // 0..15 base; +16 per 128-thread step
    const int pcc  = tid & 7;
#define PREFETCH(stage, kt)                                                     \
    do {                                                                        \
        uint32_t ab = sb + (stage) * STAGE_BYTES;                               \
        _Pragma("unroll")                                                       \
        for (int j = 0; j < 8; j++) {        /* A: 128 rows */                  \
            int row = prow + j * 16;                                            \
            uint32_t dst = ab + (uint32_t)(row * 128 + ((pcc * 16) ^ ((row & 7) * 16))); \
            cpasync16(dst, A + (size_t)(m0 + row) * K + (kt) + pcc * 8);        \
        }                                                                       \
        _Pragma("unroll")                                                       \
        for (int j = 0; j < 8; j++) {        /* B: 128 rows */                  \
            int row = prow + j * 16;                                            \
            int gn = n0 + row;                                                  \
            uint32_t dst = ab + 16384u + (uint32_t)(row * 128 + ((pcc * 16) ^ ((row & 7) * 16))); \
            int gnc = gn < N ? gn : N - 1;                                      \
            cpasync16z(dst, B + (size_t)gnc * K + (kt) + pcc * 8,               \
                       gn < N ? 16u : 0u);                                      \
        }                                                                       \
        CP_COMMIT();                                                            \
    } while (0)

    PREFETCH(0, 0);
    PREFETCH(1, KC);

    for (int c = 0; c < nch; c++) {
        if (c + 2 < nch) PREFETCH((c + 2) % 3, (c + 2) * KC);
        if (c + 2 < nch)      asm volatile("cp.async.wait_group 2;" ::: "memory");
        else if (c + 1 < nch) asm volatile("cp.async.wait_group 1;" ::: "memory");
        else                  asm volatile("cp.async.wait_group 0;" ::: "memory");
        __syncthreads();

        const uint32_t As = sb + (c % 3) * STAGE_BYTES;
        const uint32_t Bs = As + 16384;
#pragma unroll
        for (int ks = 0; ks < 4; ks++) {
            uint32_t a[4][4], b[4][4];
#pragma unroll
            for (int mt = 0; mt < 4; mt++)
                ldsm4(a[mt], As + (uint32_t)((rowA + mt * 16) * 128 + ((ks * 32) ^ kxA)));
#pragma unroll
            for (int j = 0; j < 4; j++)
                ldsm4(b[j], Bs + (uint32_t)((rowB + j * 16) * 128 + ((ks * 32) ^ kxB)));
#pragma unroll
            for (int mt = 0; mt < 4; mt++)
#pragma unroll
                for (int nt = 0; nt < 8; nt++)
                    mma16816(acc[mt][nt], a[mt],
                             b[nt >> 1][(nt & 1) * 2], b[nt >> 1][(nt & 1) * 2 + 1]);
        }
        __syncthreads();
    }

    const int mrow  = m0 + wm * 64 + (lane >> 2);
    const int ncol0 = n0 + wn * 64 + (lane & 3) * 2;
#pragma unroll
    for (int mt = 0; mt < 4; mt++) {
#pragma unroll
        for (int nt = 0; nt < 8; nt++) {
            int cc = ncol0 + nt * 8;
            if (cc < N) {
                float b0v = bias0[cc], b1v = bias0[cc + 1];
                if (bias1) { b0v += bias1[cc]; b1v += bias1[cc + 1]; }
                int r0 = mrow + mt * 16;
                float2 v0 = make_float2(acc[mt][nt][0] + b0v, acc[mt][nt][1] + b1v);
                float2 v1 = make_float2(acc[mt][nt][2] + b0v, acc[mt][nt][3] + b1v);
                *(float2*)(C + (size_t)r0 * N + cc)       = v0;
                *(float2*)(C + (size_t)(r0 + 8) * N + cc) = v1;
            }
        }
    }
#undef PREFETCH
}

// ---------------- persistent LSTM, tensor-core recurrence ----------------------
// 64 CTAs x 256 threads (8 warps). CTA owns 8 hidden units -> 32 gate rows.
// W_hh (fp16) SMEM-resident. h: fp16 [32 x 512] ping-pong in L2.
// pregates tile for step t+1 prefetched into double-buffered SMEM during step t.
#define LWS_OFF  0
#define LHS_OFF  32768
#define LPG_OFF  65536                        // 2 x 4KB pregates buffers
#define LGSM_OFF (65536 + 8192)
#define LCSM_OFF (LGSM_OFF + 32 * 33 * 4)
#define LSM_BYTES (LCSM_OFF + 256 * 4)

__device__ __forceinline__ float sigf(float x) { return 1.0f / (1.0f + expf(-x)); }

__global__ __launch_bounds__(256, 1) void lstm_persistent(
    const float* __restrict__ pregates,
    const __half* __restrict__ Whh2,
    __half* __restrict__ hA, __half* __restrict__ hB,
    __half* __restrict__ H2, int* __restrict__ bar)
{
    extern __shared__ char smem[];
    const uint32_t sb = smem_u32(smem);
    float* gsm = (float*)(smem + LGSM_OFF);
    float* csm = (float*)(smem + LCSM_OFF);

    const int tid  = threadIdx.x;
    const int lane = tid & 31, wid = tid >> 5;
    const int u0   = blockIdx.x * 8;

    // pregates prefetch geometry: thread -> (b, gate, 16B-half)
    const int qb = tid >> 3, qg = (tid >> 1) & 3, qh = tid & 1;
    const size_t qsrc_base = (size_t)qb * TT * G4 + qg * 512 + u0 + qh * 4;
    const uint32_t qdst_off = (uint32_t)(qb * 128 + qg * 32 + qh * 16);

    // stage 32 gate rows of W_hh (fp16) once
    for (int i = tid; i < 2048; i += 256) {
        int rr = i >> 6, cq = i & 63;
        int g = rr >> 3, ul = rr & 7;
        uint32_t dst = sb + LWS_OFF + (uint32_t)(rr * 1024 + ((cq * 16) ^ ((rr & 7) * 16)));
        cpasync16(dst, Whh2 + (size_t)(g * 512 + u0 + ul) * HID + cq * 8);
    }
    CP_COMMIT();
    // prefetch pregates for t = 0 into buffer 0
    cpasync16(sb + LPG_OFF + qdst_off, pregates + qsrc_base);
    CP_COMMIT();
    csm[tid] = 0.0f;

    // warp geometry
    const int wm = wid & 1, wn = wid >> 1;
    const int rowA = wm * 16 + (lane & 15);
    const int kxA  = (lane >> 4) * 16;
    const int sxA  = (rowA & 7) * 16;
    const int rowB = wn * 8 + (lane & 7);
    const int kxB  = ((lane >> 3) & 3) * 16;
    const int sxB  = (rowB & 7) * 16;
    const uint32_t wsb = sb + LWS_OFF, hsb = sb + LHS_OFF;

    const int pb = tid >> 3, pul = tid & 7;
    const int pu = u0 + pul;

    for (int t = 0; t < TT; t++) {
        // stage h (fp16 32x512) into swizzled SMEM
        const __half* hin = (t & 1) ? hB : hA;
        for (int i = tid; i < 2048; i += 256) {
            int b = i >> 6, cq = i & 63;
            uint32_t dst = hsb + (uint32_t)(b * 1024 + ((cq * 16) ^ ((b & 7) * 16)));
            cpasync16(dst, hin + b * HID + cq * 8);
        }
        CP_COMMIT();
        if (t + 1 < TT) {
            // prefetch pregates(t+1) into the other buffer; stays in flight
            cpasync16(sb + LPG_OFF + ((t + 1) & 1) * 4096 + qdst_off,
                      pregates + qsrc_base + (size_t)(t + 1) * G4);
            CP_COMMIT();
            asm volatile("cp.async.wait_group 1;" ::: "memory");
        } else {
            asm volatile("cp.async.wait_group 0;" ::: "memory");
        }
        __syncthreads();

        // MMA: [32 gate-rows x 32 batch] = Ws[32x512] * hs[32x512]^T
        float c0[4] = {0.f, 0.f, 0.f, 0.f}, c1[4] = {0.f, 0.f, 0.f, 0.f};
#pragma unroll
        for (int ks2 = 0; ks2 < 16; ks2++) {
            uint32_t bf[4], a0[4], a1[4];
            ldsm4(bf, hsb + (uint32_t)(rowB * 1024 + ((ks2 * 64 + kxB) ^ sxB)));
            ldsm4(a0, wsb + (uint32_t)(rowA * 1024 + ((ks2 * 64 + kxA) ^ sxA)));
            ldsm4(a1, wsb + (uint32_t)(rowA * 1024 + ((ks2 * 64 + 32 + kxA) ^ sxA)));
            mma16816(c0, a0, bf[0], bf[1]);
            mma16816(c1, a1, bf[2], bf[3]);
        }
#pragma unroll
        for (int e = 0; e < 4; e++) c0[e] += c1[e];
        {
            int r0 = wm * 16 + (lane >> 2);
            int cc = wn * 8 + (lane & 3) * 2;
            gsm[r0 * 33 + cc]           = c0[0];
            gsm[r0 * 33 + cc + 1]       = c0[1];
            gsm[(r0 + 8) * 33 + cc]     = c0[2];
            gsm[(r0 + 8) * 33 + cc + 1] = c0[3];
        }
        __syncthreads();

        // pointwise: 256 threads = 32 b x 8 units; pregates from SMEM buffer
        {
            const float* pgs = (const float*)(smem + LPG_OFF + (t & 1) * 4096);
            float gi = gsm[(0  + pul) * 33 + pb] + pgs[pb * 32 + 0 * 8 + pul];
            float gf = gsm[(8  + pul) * 33 + pb] + pgs[pb * 32 + 1 * 8 + pul];
            float gg = gsm[(16 + pul) * 33 + pb] + pgs[pb * 32 + 2 * 8 + pul];
            float go = gsm[(24 + pul) * 33 + pb] + pgs[pb * 32 + 3 * 8 + pul];
            float c_old = csm[tid];
            float cn = sigf(gf) * c_old + sigf(gi) * tanhf(gg);
            float hn = sigf(go) * tanhf(cn);
            csm[tid] = cn;
            __half hh = __float2half(hn);
            __half* hout = (t & 1) ? hA : hB;
            hout[pb * HID + pu] = hh;
            H2[((size_t)pb * TT + t) * HID + pu] = hh;
        }

        if (t < TT - 1) {
            __threadfence();
            __syncthreads();
            if (tid == 0) {
                atomicAdd(bar, 1);
                int target = 64 * (t + 1);
                while (*((volatile int*)bar) < target) { }
            }
            __syncthreads();
            __threadfence();
        }
    }
}

// ---------------- launch ------------------------------------------------------
extern "C" void kernel_launch(void* const* d_in, const int* in_sizes, int n_in,
                              void* d_out, int out_size)
{
    const float* enc       = (const float*)d_in[0];
    const int*   captions  = (const int*)  d_in[1];
    const float* emb_table = (const float*)d_in[8];
    const float* W_ih      = (const float*)d_in[9];
    const float* W_hh      = (const float*)d_in[10];
    const float* b_ih      = (const float*)d_in[11];
    const float* b_hh      = (const float*)d_in[12];
    const float* W_fc      = (const float*)d_in[13];
    const float* b_fc      = (const float*)d_in[14];
    float* out = (float*)d_out;

    __half *pX2, *pWih2, *pWhh2, *pWfc2, *pH2, *ph2A, *ph2B;
    float *pPG;
    int* pBar;
    cudaGetSymbolAddress((void**)&pX2, g_X2);
    cudaGetSymbolAddress((void**)&pWih2, g_Wih2);
    cudaGetSymbolAddress((void**)&pWhh2, g_Whh2);
    cudaGetSymbolAddress((void**)&pWfc2, g_Wfc2);
    cudaGetSymbolAddress((void**)&pH2, g_H2);
    cudaGetSymbolAddress((void**)&ph2A, g_h2A);
    cudaGetSymbolAddress((void**)&ph2B, g_h2B);
    cudaGetSymbolAddress((void**)&pPG, g_pg);
    cudaGetSymbolAddress((void**)&pBar, g_bar);

    cudaFuncSetAttribute(hmma_gemm, cudaFuncAttributeMaxDynamicSharedMemorySize, GSMEM);
    cudaFuncSetAttribute(lstm_persistent, cudaFuncAttributeMaxDynamicSharedMemorySize, LSM_BYTES);

    // 1) fp32 -> fp16 weight converts
    cvt2h_kernel<<<(G4 * XD / 2 + 255) / 256, 256>>>(W_ih, pWih2, G4 * XD / 2);
    cvt2h_kernel<<<(G4 * HID / 2 + 255) / 256, 256>>>(W_hh, pWhh2, G4 * HID / 2);
    cvt2h_kernel<<<(VV * HID / 2 + 255) / 256, 256>>>(W_fc, pWfc2, VV * HID / 2);

    // 2) build X2, zero FULL h ping + barrier reset
    prep_kernel<<<MROWS + 32, 256>>>(enc, captions, emb_table, pX2, ph2A, pBar);

    // 3) pregates = X @ W_ih^T + b_ih + b_hh   (K = 768)
    {
        dim3 grid(G4 / 128, MROWS / 128);
        hmma_gemm<<<grid, 128, GSMEM>>>(pX2, pWih2, pPG, b_ih, b_hh,
                                        MROWS, G4, XD);
    }

    // 4) persistent tensor-core LSTM (one launch, emits H2 inline)
    lstm_persistent<<<64, 256, LSM_BYTES>>>(pPG, pWhh2, ph2A, ph2B, pH2, pBar);

    // 5) out = H @ W_fc^T + b_fc   (K = 512)
    {
        dim3 grid((VV + 127) / 128, MROWS / 128);
        hmma_gemm<<<grid, 128, GSMEM>>>(pH2, pWfc2, out, b_fc, nullptr,
                                        MROWS, VV, HID);
    }
}